// round 14
// baseline (speedup 1.0000x reference)
#include <cuda_runtime.h>
#include <cuda_fp16.h>
#include <cstdint>

// ---------------------------------------------------------------------------
// Problem constants
// ---------------------------------------------------------------------------
#define BS      2
#define SEQ     4096
#define DMODEL  768
#define HEADS   12
#define DK      64
#define MROWS   (BS * SEQ)          // 8192

// ---------------------------------------------------------------------------
// Scratch (device globals; no cudaMalloc allowed)
// ---------------------------------------------------------------------------
__device__ __half g_qh[MROWS * DMODEL];              // fp16 copies of q,k,v
__device__ __half g_kh[MROWS * DMODEL];
__device__ __half g_vh[MROWS * DMODEL];
__device__ __half g_Wh[4][DMODEL * DMODEL];          // fp16 Wq,Wk,Wv,Wo
__device__ __half g_Qp[MROWS * DMODEL];              // prescaled by log2e/8
__device__ __half g_Kp[MROWS * DMODEL];
__device__ __half g_Vt[(size_t)BS * DMODEL * SEQ];   // [b][dmodel][seq]
__device__ __half g_Ctx[MROWS * DMODEL];
__device__ int    g_ticket;                          // persistent-attn ticket

// ---------------------------------------------------------------------------
// Helpers
// ---------------------------------------------------------------------------
__device__ __forceinline__ void mma16(float* d, const uint32_t* a,
                                      uint32_t b0, uint32_t b1) {
    asm volatile(
        "mma.sync.aligned.m16n8k16.row.col.f32.f16.f16.f32 "
        "{%0,%1,%2,%3}, {%4,%5,%6,%7}, {%8,%9}, {%0,%1,%2,%3};"
        : "+f"(d[0]), "+f"(d[1]), "+f"(d[2]), "+f"(d[3])
        : "r"(a[0]), "r"(a[1]), "r"(a[2]), "r"(a[3]), "r"(b0), "r"(b1));
}

__device__ __forceinline__ uint32_t packh2(float a, float b) {
    __half2 h = __floats2half2_rn(a, b);
    return *(uint32_t*)&h;
}

__device__ __forceinline__ uint32_t ex2h2(uint32_t x) {
    uint32_t r;
    asm("ex2.approx.f16x2 %0, %1;" : "=r"(r) : "r"(x));
    return r;
}

__device__ __forceinline__ void st_h4(__half* p, float4 v) {
    uint2 u;
    u.x = packh2(v.x, v.y);
    u.y = packh2(v.z, v.w);
    *(uint2*)p = u;
}

__device__ __forceinline__ void cpa16r(uint32_t dst, const void* src) {
    asm volatile("cp.async.cg.shared.global [%0], [%1], 16;"
                 :: "r"(dst), "l"(src));
}
#define CPA_COMMIT() asm volatile("cp.async.commit_group;" ::: "memory")
#define CPA_WAIT1()  asm volatile("cp.async.wait_group 1;" ::: "memory")
#define CPA_WAIT0()  asm volatile("cp.async.wait_group 0;" ::: "memory")

// ---------------------------------------------------------------------------
// fp32 -> fp16 conversion passes (one-time, DRAM-bound)
// ---------------------------------------------------------------------------
__global__ __launch_bounds__(256) void cvt_act(
    const float* __restrict__ q, const float* __restrict__ k,
    const float* __restrict__ v,
    __half* __restrict__ qh, __half* __restrict__ kh, __half* __restrict__ vh)
{
    const float* s = (blockIdx.y == 0) ? q : (blockIdx.y == 1) ? k : v;
    __half* d      = (blockIdx.y == 0) ? qh : (blockIdx.y == 1) ? kh : vh;
    const int i = (blockIdx.x * 256 + threadIdx.x) * 4;
    st_h4(d + i, *(const float4*)(s + i));
}

__global__ __launch_bounds__(256) void cvt_w(
    const float* __restrict__ Wq, const float* __restrict__ Wk,
    const float* __restrict__ Wv, const float* __restrict__ Wo,
    __half* __restrict__ Wh)
{
    const float* s = (blockIdx.y == 0) ? Wq : (blockIdx.y == 1) ? Wk
                   : (blockIdx.y == 2) ? Wv : Wo;
    __half* d = Wh + (size_t)blockIdx.y * (DMODEL * DMODEL);
    const int i = (blockIdx.x * 256 + threadIdx.x) * 4;
    st_h4(d + i, *(const float4*)(s + i));
}

// ---------------------------------------------------------------------------
// GEMM body (fp16 in): C[M,N] = (A @ B^T + bias)*scale
// 128x128 CTA tile, 128 threads = 4 warps with 64x64 warp tiles (2m x 2n),
// BK=32, cp.async double-buffered k-loop. 1.0 LDS per mma.
// trans!=0: write C transposed per batch (Vt layout).
// ---------------------------------------------------------------------------
#define GBM 128
#define GBN 128
#define GBK 32
#define GLDH 40
#define GBUF (128 * GLDH * 2)     // bytes per stage buffer

template <typename OutT>
__device__ __forceinline__ void gemm_body_h(
    const __half* __restrict__ A, const __half* __restrict__ B,
    const float* __restrict__ bias, OutT* __restrict__ C,
    float scale, int trans, __half* As, __half* Bs)   // As,Bs: [2][128*GLDH]
{
    const int N = DMODEL, K = DMODEL;
    const int tid = threadIdx.x;
    const int lane = tid & 31, wid = tid >> 5;        // 4 warps
    const int g = lane >> 2, tig = lane & 3;
    const int wm = (wid & 1) * 64, wn = (wid >> 1) * 64;
    const int row0 = blockIdx.y * GBM, col0 = blockIdx.x * GBN;

    // cp.async mapping: thread tid -> row tid, 4 x 16B chunks (32 halves)
    const __half* Aptr = A + (size_t)(row0 + tid) * K;
    const __half* Bptr = B + (size_t)(col0 + tid) * K;
    const uint32_t dA = (uint32_t)__cvta_generic_to_shared(As + tid * GLDH);
    const uint32_t dB = (uint32_t)__cvta_generic_to_shared(Bs + tid * GLDH);

    // prefetch k-tile 0 into buffer 0
    #pragma unroll
    for (int ch = 0; ch < 4; ch++) {
        cpa16r(dA + ch * 16, Aptr + ch * 8);
        cpa16r(dB + ch * 16, Bptr + ch * 8);
    }
    CPA_COMMIT();

    float acc[4][8][4] = {};
    const int NKT = K / GBK;   // 24

    for (int kt = 0; kt < NKT; kt++) {
        const int cur = kt & 1;
        if (kt + 1 < NKT) {
            const int off = (kt + 1) * GBK;
            const uint32_t a2 = dA + (cur ^ 1) * GBUF;
            const uint32_t b2 = dB + (cur ^ 1) * GBUF;
            #pragma unroll
            for (int ch = 0; ch < 4; ch++) {
                cpa16r(a2 + ch * 16, Aptr + off + ch * 8);
                cpa16r(b2 + ch * 16, Bptr + off + ch * 8);
            }
            CPA_COMMIT();
            CPA_WAIT1();
        } else {
            CPA_WAIT0();
        }
        __syncthreads();

        const __half* Asc = As + cur * (128 * GLDH);
        const __half* Bsc = Bs + cur * (128 * GLDH);
        #pragma unroll
        for (int c = 0; c < 2; c++) {
            const int kk = 16 * c + 2 * tig;
            uint32_t a[4][4];
            #pragma unroll
            for (int i = 0; i < 4; i++) {
                const int rb = wm + 16 * i;
                a[i][0] = *(const uint32_t*)&Asc[(rb + g) * GLDH + kk];
                a[i][1] = *(const uint32_t*)&Asc[(rb + 8 + g) * GLDH + kk];
                a[i][2] = *(const uint32_t*)&Asc[(rb + g) * GLDH + kk + 8];
                a[i][3] = *(const uint32_t*)&Asc[(rb + 8 + g) * GLDH + kk + 8];
            }
            #pragma unroll
            for (int j = 0; j < 8; j++) {
                const int cn = wn + j * 8 + g;
                uint32_t b0 = *(const uint32_t*)&Bsc[cn * GLDH + kk];
                uint32_t b1 = *(const uint32_t*)&Bsc[cn * GLDH + kk + 8];
                #pragma unroll
                for (int i = 0; i < 4; i++)
                    mma16(acc[i][j], a[i], b0, b1);
            }
        }
        __syncthreads();    // compute done before next prefetch overwrites
    }

    #pragma unroll
    for (int i = 0; i < 4; i++) {
        const int rA = row0 + wm + i * 16 + g;
        const int rB = rA + 8;
        #pragma unroll
        for (int j = 0; j < 8; j++) {
            const int col = col0 + wn + j * 8 + 2 * tig;
            const float bx = __ldg(bias + col), by = __ldg(bias + col + 1);
            const float v0 = (acc[i][j][0] + bx) * scale;
            const float v1 = (acc[i][j][1] + by) * scale;
            const float v2 = (acc[i][j][2] + bx) * scale;
            const float v3 = (acc[i][j][3] + by) * scale;
            if (!trans) {
                if (sizeof(OutT) == 2) {
                    __half2* pA = (__half2*)((__half*)C + (size_t)rA * N + col);
                    __half2* pB = (__half2*)((__half*)C + (size_t)rB * N + col);
                    *pA = __floats2half2_rn(v0, v1);
                    *pB = __floats2half2_rn(v2, v3);
                } else {
                    *(float2*)((float*)C + (size_t)rA * N + col) = make_float2(v0, v1);
                    *(float2*)((float*)C + (size_t)rB * N + col) = make_float2(v2, v3);
                }
            } else {
                const int bA = rA >> 12, sA = rA & (SEQ - 1);
                const int bB = rB >> 12, sB = rB & (SEQ - 1);
                C[((size_t)bA * DMODEL + col)     * SEQ + sA] = (OutT)v0;
                C[((size_t)bA * DMODEL + col + 1) * SEQ + sA] = (OutT)v1;
                C[((size_t)bB * DMODEL + col)     * SEQ + sB] = (OutT)v2;
                C[((size_t)bB * DMODEL + col + 1) * SEQ + sB] = (OutT)v3;
            }
        }
    }
}

// merged Q/K/V projection: blockIdx.z selects the GEMM
__global__ __launch_bounds__(128, 2) void qkv_gemm(
    const __half* __restrict__ qh, const __half* __restrict__ kh,
    const __half* __restrict__ vh, const __half* __restrict__ Wh,
    const float* __restrict__ bq, const float* __restrict__ bk,
    const float* __restrict__ bv,
    __half* __restrict__ Qp, __half* __restrict__ Kp, __half* __restrict__ Vt,
    float qscale)
{
    __shared__ __half As[2][128 * GLDH];
    __shared__ __half Bs[2][128 * GLDH];
    const int z = blockIdx.z;
    const __half* A  = (z == 0) ? qh : (z == 1) ? kh : vh;
    const __half* W  = Wh + (size_t)z * (DMODEL * DMODEL);
    const float* bb  = (z == 0) ? bq : (z == 1) ? bk : bv;
    __half* C        = (z == 0) ? Qp : (z == 1) ? Kp : Vt;
    const float sc   = (z == 0) ? qscale : 1.0f;
    gemm_body_h<__half>(A, W, bb, C, sc, z == 2, As[0], Bs[0]);
}

__global__ __launch_bounds__(128, 2) void o_gemm(
    const __half* __restrict__ Ctx, const __half* __restrict__ Wh,
    const float* __restrict__ bo, float* __restrict__ out)
{
    __shared__ __half As[2][128 * GLDH];
    __shared__ __half Bs[2][128 * GLDH];
    gemm_body_h<float>(Ctx, Wh + (size_t)3 * (DMODEL * DMODEL), bo, out,
                       1.0f, 0, As[0], Bs[0]);
}

// ---------------------------------------------------------------------------
// Attention: PERSISTENT CTAs + atomic ticket (wave-quantization fix) around
// the Round-11 proven body: fp16 mma, 32-q warp tiles, 2-stage cp.async,
// exp2-domain softmax via ex2.f16x2, row sums via ones-MMA. fp16 Ctx out.
// Unit u (0..767): bh = u>>5 (ticket-major: concurrent CTAs share K/V in L2),
// qtile = u&31.
// ---------------------------------------------------------------------------
#define KLD 72
#define NT  (SEQ / 64)
#define BUFB (128 * KLD * 2)      // bytes per KV buffer
#define NUNITS (BS * HEADS * (SEQ / 128))   // 768

__global__ void __launch_bounds__(128, 3)
attn_tc(const __half* __restrict__ Qp, const __half* __restrict__ Kp,
        const __half* __restrict__ Vt, const int* __restrict__ mask,
        __half* __restrict__ Ctx)
{
    __shared__ __half KV[2][128 * KLD];
    __shared__ int s_u;

    const int tid = threadIdx.x;
    const int lane = tid & 31, wid = tid >> 5;
    const int g = lane >> 2, tig = lane & 3;
    const uint32_t ONE2 = 0x3C003C00u;
    const float NEGINF = __int_as_float(0xff800000);

    for (;;) {
        if (tid == 0) s_u = atomicAdd(&g_ticket, 1);
        __syncthreads();
        const int u = s_u;
        if (u >= NUNITS) break;

        const int bh = u >> 5, qt = u & 31;
        const int b = bh / HEADS, h = bh % HEADS;
        const int q0 = qt * 128;
        const int qb = wid * 32;

        const __half* kg = Kp + ((size_t)b * SEQ) * DMODEL + h * DK;
        const __half* vg = Vt + ((size_t)(b * DMODEL + h * DK)) * SEQ;
        const int* mg = mask + b * SEQ;

        // ---- stage Q through KV[0], lift A-frags ----
        {
            const __half* qg = Qp + ((size_t)(b * SEQ + q0)) * DMODEL + h * DK;
            #pragma unroll
            for (int i = 0; i < 8; i++) {
                const int L = tid + i * 128;
                const int r = L >> 3, c8 = (L & 7) * 8;
                *(uint4*)(KV[0] + r * KLD + c8) =
                    *(const uint4*)(qg + (size_t)r * DMODEL + c8);
            }
        }
        __syncthreads();

        uint32_t qf[4][2][4];
        #pragma unroll
        for (int c = 0; c < 4; c++) {
            const int kk = 16 * c + 2 * tig;
            #pragma unroll
            for (int i = 0; i < 2; i++) {
                const int rb = qb + 16 * i;
                qf[c][i][0] = *(const uint32_t*)&KV[0][(rb + g) * KLD + kk];
                qf[c][i][1] = *(const uint32_t*)&KV[0][(rb + 8 + g) * KLD + kk];
                qf[c][i][2] = *(const uint32_t*)&KV[0][(rb + g) * KLD + kk + 8];
                qf[c][i][3] = *(const uint32_t*)&KV[0][(rb + 8 + g) * KLD + kk + 8];
            }
        }
        __syncthreads();

        // ---- hoisted prefetch addressing ----
        const int pr = tid >> 3;
        const int pc = (tid & 7) * 8;
        const __half* ksrc = kg + (size_t)pr * DMODEL + pc;
        const __half* vsrc = vg + (size_t)pr * SEQ + pc;
        const uint32_t dk0 =
            (uint32_t)__cvta_generic_to_shared(&KV[0][pr * KLD + pc]);

        float o[2][8][4] = {};
        float lacc[2][4] = {};

        // prefetch tile 0 into buffer 0
        {
            const uint32_t dV = dk0 + 64 * KLD * 2;
            #pragma unroll
            for (int i = 0; i < 4; i++) {
                cpa16r(dk0 + i * (16 * KLD * 2), ksrc + (size_t)i * 16 * DMODEL);
                cpa16r(dV + i * (16 * KLD * 2), vsrc + (size_t)i * 16 * SEQ);
            }
            CPA_COMMIT();
            ksrc += (size_t)64 * DMODEL;
            vsrc += 64;
        }

        for (int kt = 0; kt < NT; kt++) {
            const int cur = kt & 1;
            const __half* Ks = KV[cur];
            const __half* Vs = KV[cur] + 64 * KLD;

            const int mv = __ldg(mg + kt * 64 + (tid & 63));

            if (kt + 1 < NT) {
                const uint32_t dK = dk0 + (cur ^ 1) * BUFB;
                const uint32_t dV = dK + 64 * KLD * 2;
                #pragma unroll
                for (int i = 0; i < 4; i++) {
                    cpa16r(dK + i * (16 * KLD * 2),
                           ksrc + (size_t)i * 16 * DMODEL);
                    cpa16r(dV + i * (16 * KLD * 2),
                           vsrc + (size_t)i * 16 * SEQ);
                }
                CPA_COMMIT();
                ksrc += (size_t)64 * DMODEL;
                vsrc += 64;
                CPA_WAIT1();
            } else {
                CPA_WAIT0();
            }
            const int allone = __syncthreads_and(mv != 0);

            // ---- S = Q K^T (exp2-domain scores) ----
            float s[2][8][4] = {};
            #pragma unroll
            for (int c = 0; c < 4; c++) {
                const int kk = 16 * c + 2 * tig;
                #pragma unroll
                for (int j = 0; j < 8; j++) {
                    const int rn = (j * 8 + g) * KLD + kk;
                    uint32_t b0 = *(const uint32_t*)&Ks[rn];
                    uint32_t b1 = *(const uint32_t*)&Ks[rn + 8];
                    mma16(s[0][j], qf[c][0], b0, b1);
                    mma16(s[1][j], qf[c][1], b0, b1);
                }
            }

            if (!allone) {
                #pragma unroll
                for (int j = 0; j < 8; j++) {
                    int2 mi = __ldg((const int2*)(mg + kt * 64 + j * 8 + 2 * tig));
                    if (!mi.x) {
                        s[0][j][0] = NEGINF; s[0][j][2] = NEGINF;
                        s[1][j][0] = NEGINF; s[1][j][2] = NEGINF;
                    }
                    if (!mi.y) {
                        s[0][j][1] = NEGINF; s[0][j][3] = NEGINF;
                        s[1][j][1] = NEGINF; s[1][j][3] = NEGINF;
                    }
                }
            }

            // ---- p = exp2(s) in f16x2; result IS the P fragment ----
            uint32_t pa[2][8][2];
            #pragma unroll
            for (int j = 0; j < 8; j++) {
                pa[0][j][0] = ex2h2(packh2(s[0][j][0], s[0][j][1]));
                pa[0][j][1] = ex2h2(packh2(s[0][j][2], s[0][j][3]));
                pa[1][j][0] = ex2h2(packh2(s[1][j][0], s[1][j][1]));
                pa[1][j][1] = ex2h2(packh2(s[1][j][2], s[1][j][3]));
            }

            // ---- O += P V^T ; l += P·1 (ones-MMA) ----
            #pragma unroll
            for (int m = 0; m < 4; m++) {
                uint32_t av0[4] = { pa[0][2 * m][0], pa[0][2 * m][1],
                                    pa[0][2 * m + 1][0], pa[0][2 * m + 1][1] };
                uint32_t av1[4] = { pa[1][2 * m][0], pa[1][2 * m][1],
                                    pa[1][2 * m + 1][0], pa[1][2 * m + 1][1] };
                const int kk = 16 * m + 2 * tig;
                #pragma unroll
                for (int j = 0; j < 8; j++) {
                    const int rn = (j * 8 + g) * KLD + kk;
                    uint32_t b0 = *(const uint32_t*)&Vs[rn];
                    uint32_t b1 = *(const uint32_t*)&Vs[rn + 8];
                    mma16(o[0][j], av0, b0, b1);
                    mma16(o[1][j], av1, b0, b1);
                }
                mma16(lacc[0], av0, ONE2, ONE2);
                mma16(lacc[1], av1, ONE2, ONE2);
            }
            __syncthreads();
        }

        // ---- finalize: Ctx written as fp16 ----
        const float inv[2][2] = { {1.f / lacc[0][0], 1.f / lacc[0][2]},
                                  {1.f / lacc[1][0], 1.f / lacc[1][2]} };

        #pragma unroll
        for (int i = 0; i < 2; i++) {
            __half* cg = Ctx + ((size_t)(b * SEQ + q0 + qb + 16 * i)) * DMODEL
                       + h * DK;
            #pragma unroll
            for (int j = 0; j < 8; j++) {
                const int col = j * 8 + 2 * tig;
                *(__half2*)(cg + (size_t)g * DMODEL + col) =
                    __floats2half2_rn(o[i][j][0] * inv[i][0],
                                      o[i][j][1] * inv[i][0]);
                *(__half2*)(cg + (size_t)(8 + g) * DMODEL + col) =
                    __floats2half2_rn(o[i][j][2] * inv[i][1],
                                      o[i][j][3] * inv[i][1]);
            }
        }
    }
}

// ---------------------------------------------------------------------------
// Launcher.  Inputs: q, k, v, Wq, bq, Wk, bk, Wv, bv, Wo, bo, mask
// ---------------------------------------------------------------------------
extern "C" void kernel_launch(void* const* d_in, const int* in_sizes, int n_in,
                              void* d_out, int out_size)
{
    const float* q    = (const float*)d_in[0];
    const float* k    = (const float*)d_in[1];
    const float* v    = (const float*)d_in[2];
    const float* Wq   = (const float*)d_in[3];
    const float* bq   = (const float*)d_in[4];
    const float* Wk   = (const float*)d_in[5];
    const float* bk   = (const float*)d_in[6];
    const float* Wv   = (const float*)d_in[7];
    const float* bv   = (const float*)d_in[8];
    const float* Wo   = (const float*)d_in[9];
    const float* bo   = (const float*)d_in[10];
    const int*   mask = (const int*)d_in[11];
    float* out = (float*)d_out;

    __half *qh, *kh, *vh, *Wh, *Qp, *Kp, *Vt, *Ctx;
    int* ticket;
    cudaGetSymbolAddress((void**)&qh,  g_qh);
    cudaGetSymbolAddress((void**)&kh,  g_kh);
    cudaGetSymbolAddress((void**)&vh,  g_vh);
    cudaGetSymbolAddress((void**)&Wh,  g_Wh);
    cudaGetSymbolAddress((void**)&Qp,  g_Qp);
    cudaGetSymbolAddress((void**)&Kp,  g_Kp);
    cudaGetSymbolAddress((void**)&Vt,  g_Vt);
    cudaGetSymbolAddress((void**)&Ctx, g_Ctx);
    cudaGetSymbolAddress((void**)&ticket, g_ticket);

    // Q scale folds 1/sqrt(dk) AND log2(e)
    const float qscale = 0.125f * 1.44269504088896340736f;

    // reset the persistent-attention ticket (graph-capturable async memset)
    cudaMemsetAsync(ticket, 0, sizeof(int));

    // one-time fp32 -> fp16 conversions
    dim3 agrid_cvt(MROWS * DMODEL / 4 / 256, 3);   // (6144, 3)
    cvt_act<<<agrid_cvt, 256>>>(q, k, v, qh, kh, vh);
    dim3 wgrid_cvt(DMODEL * DMODEL / 4 / 256, 4);  // (576, 4)
    cvt_w<<<wgrid_cvt, 256>>>(Wq, Wk, Wv, Wo, Wh);

    dim3 qkvgrid(DMODEL / GBN, MROWS / GBM, 3);    // (6, 64, 3)
    qkv_gemm<<<qkvgrid, 128>>>(qh, kh, vh, Wh, bq, bk, bv,
                               Qp, Kp, Vt, qscale);

    attn_tc<<<444, 128>>>(Qp, Kp, Vt, mask, Ctx);  // 148 SMs x 3 CTAs

    dim3 ogrid(DMODEL / GBN, MROWS / GBM);         // (6, 64)
    o_gemm<<<ogrid, 128>>>(Ctx, Wh, bo, out);
}

// round 15
// speedup vs baseline: 1.1392x; 1.1392x over previous
#include <cuda_runtime.h>
#include <cuda_fp16.h>
#include <cstdint>

// ---------------------------------------------------------------------------
// Problem constants
// ---------------------------------------------------------------------------
#define BS      2
#define SEQ     4096
#define DMODEL  768
#define HEADS   12
#define DK      64
#define MROWS   (BS * SEQ)          // 8192

// ---------------------------------------------------------------------------
// Scratch (device globals; no cudaMalloc allowed)
// ---------------------------------------------------------------------------
__device__ __half g_Qp[MROWS * DMODEL];              // prescaled by log2e/8
__device__ __half g_Kp[MROWS * DMODEL];
__device__ __half g_Vt[(size_t)BS * DMODEL * SEQ];   // [b][dmodel][seq]
__device__ float  g_Ctx[MROWS * DMODEL];

// ---------------------------------------------------------------------------
// Helpers
// ---------------------------------------------------------------------------
__device__ __forceinline__ void mma16(float* d, const uint32_t* a,
                                      uint32_t b0, uint32_t b1) {
    asm volatile(
        "mma.sync.aligned.m16n8k16.row.col.f32.f16.f16.f32 "
        "{%0,%1,%2,%3}, {%4,%5,%6,%7}, {%8,%9}, {%0,%1,%2,%3};"
        : "+f"(d[0]), "+f"(d[1]), "+f"(d[2]), "+f"(d[3])
        : "r"(a[0]), "r"(a[1]), "r"(a[2]), "r"(a[3]), "r"(b0), "r"(b1));
}

__device__ __forceinline__ uint32_t packh2(float a, float b) {
    __half2 h = __floats2half2_rn(a, b);
    return *(uint32_t*)&h;
}

__device__ __forceinline__ uint32_t ex2h2(uint32_t x) {
    uint32_t r;
    asm("ex2.approx.f16x2 %0, %1;" : "=r"(r) : "r"(x));
    return r;
}

__device__ __forceinline__ void st_h4(__half* p, float4 v) {
    uint2 u;
    u.x = packh2(v.x, v.y);
    u.y = packh2(v.z, v.w);
    *(uint2*)p = u;
}

__device__ __forceinline__ void cpa16r(uint32_t dst, const void* src) {
    asm volatile("cp.async.cg.shared.global [%0], [%1], 16;"
                 :: "r"(dst), "l"(src));
}
#define CPA_COMMIT() asm volatile("cp.async.commit_group;" ::: "memory")
#define CPA_WAIT1()  asm volatile("cp.async.wait_group 1;" ::: "memory")
#define CPA_WAIT0()  asm volatile("cp.async.wait_group 0;" ::: "memory")

// ldmatrix x4: four 8x8 b16 tiles in one instruction
__device__ __forceinline__ void ldsm4(uint32_t& r0, uint32_t& r1,
                                      uint32_t& r2, uint32_t& r3,
                                      uint32_t addr) {
    asm volatile("ldmatrix.sync.aligned.m8n8.x4.shared.b16 {%0,%1,%2,%3}, [%4];"
                 : "=r"(r0), "=r"(r1), "=r"(r2), "=r"(r3) : "r"(addr));
}

// ---------------------------------------------------------------------------
// GEMM (Round-12 proven): C[M,N] = (A @ B^T + bias)*scale, fp32 in,
// fp16 smem staging, 128x128 tile, BK=32, 256 threads, warp tile 32x64.
// trans!=0: write C transposed per batch (Vt layout).
// ---------------------------------------------------------------------------
#define GBM 128
#define GBN 128
#define GBK 32
#define GLDH 40

template <typename OutT>
__device__ __forceinline__ void gemm_body(
    const float* __restrict__ A, const float* __restrict__ B,
    const float* __restrict__ bias, OutT* __restrict__ C,
    float scale, int trans, __half* As, __half* Bs)
{
    const int N = DMODEL, K = DMODEL;
    const int tid = threadIdx.x;
    const int lane = tid & 31, wid = tid >> 5;
    const int g = lane >> 2, tig = lane & 3;
    const int wm = (wid & 3) * 32, wn = (wid >> 2) * 64;
    const int row0 = blockIdx.y * GBM, col0 = blockIdx.x * GBN;

    const int r = tid >> 3;
    const int c4 = (tid & 7) * 4;
    const float* Aptr = A + (size_t)(row0 + r) * K + c4;
    const float* Bptr = B + (size_t)(col0 + r) * K + c4;

    float4 pa[4], pb[4];
    #pragma unroll
    for (int m = 0; m < 4; m++) {
        pa[m] = *(const float4*)(Aptr + (size_t)(32 * m) * K);
        pb[m] = *(const float4*)(Bptr + (size_t)(32 * m) * K);
    }

    float acc[2][8][4] = {};

    int k0 = 0;
    while (true) {
        __syncthreads();
        #pragma unroll
        for (int m = 0; m < 4; m++) {
            st_h4(As + (r + 32 * m) * GLDH + c4, pa[m]);
            st_h4(Bs + (r + 32 * m) * GLDH + c4, pb[m]);
        }
        __syncthreads();

        k0 += GBK;
        const bool more = (k0 < K);
        if (more) {
            #pragma unroll
            for (int m = 0; m < 4; m++) {
                pa[m] = *(const float4*)(Aptr + (size_t)(32 * m) * K + k0);
                pb[m] = *(const float4*)(Bptr + (size_t)(32 * m) * K + k0);
            }
        }

        #pragma unroll
        for (int c = 0; c < 2; c++) {
            const int kk = 16 * c + 2 * tig;
            uint32_t a[2][4];
            #pragma unroll
            for (int i = 0; i < 2; i++) {
                const int rb = wm + 16 * i;
                a[i][0] = *(const uint32_t*)&As[(rb + g) * GLDH + kk];
                a[i][1] = *(const uint32_t*)&As[(rb + 8 + g) * GLDH + kk];
                a[i][2] = *(const uint32_t*)&As[(rb + g) * GLDH + kk + 8];
                a[i][3] = *(const uint32_t*)&As[(rb + 8 + g) * GLDH + kk + 8];
            }
            #pragma unroll
            for (int j = 0; j < 8; j++) {
                const int cn = wn + j * 8 + g;
                uint32_t b0 = *(const uint32_t*)&Bs[cn * GLDH + kk];
                uint32_t b1 = *(const uint32_t*)&Bs[cn * GLDH + kk + 8];
                mma16(acc[0][j], a[0], b0, b1);
                mma16(acc[1][j], a[1], b0, b1);
            }
        }
        if (!more) break;
    }

    #pragma unroll
    for (int i = 0; i < 2; i++) {
        const int rA = row0 + wm + i * 16 + g;
        const int rB = rA + 8;
        #pragma unroll
        for (int j = 0; j < 8; j++) {
            const int col = col0 + wn + j * 8 + 2 * tig;
            const float bx = __ldg(bias + col), by = __ldg(bias + col + 1);
            const float v0 = (acc[i][j][0] + bx) * scale;
            const float v1 = (acc[i][j][1] + by) * scale;
            const float v2 = (acc[i][j][2] + bx) * scale;
            const float v3 = (acc[i][j][3] + by) * scale;
            if (!trans) {
                if (sizeof(OutT) == 2) {
                    __half2* pA = (__half2*)((__half*)C + (size_t)rA * N + col);
                    __half2* pB = (__half2*)((__half*)C + (size_t)rB * N + col);
                    *pA = __floats2half2_rn(v0, v1);
                    *pB = __floats2half2_rn(v2, v3);
                } else {
                    *(float2*)((float*)C + (size_t)rA * N + col) = make_float2(v0, v1);
                    *(float2*)((float*)C + (size_t)rB * N + col) = make_float2(v2, v3);
                }
            } else {
                const int bA = rA >> 12, sA = rA & (SEQ - 1);
                const int bB = rB >> 12, sB = rB & (SEQ - 1);
                C[((size_t)bA * DMODEL + col)     * SEQ + sA] = (OutT)v0;
                C[((size_t)bA * DMODEL + col + 1) * SEQ + sA] = (OutT)v1;
                C[((size_t)bB * DMODEL + col)     * SEQ + sB] = (OutT)v2;
                C[((size_t)bB * DMODEL + col + 1) * SEQ + sB] = (OutT)v3;
            }
        }
    }
}

// merged Q/K/V projection: blockIdx.z selects the GEMM
__global__ __launch_bounds__(256, 2) void qkv_gemm(
    const float* __restrict__ q, const float* __restrict__ k,
    const float* __restrict__ v,
    const float* __restrict__ Wq, const float* __restrict__ bq,
    const float* __restrict__ Wk, const float* __restrict__ bk,
    const float* __restrict__ Wv, const float* __restrict__ bv,
    __half* __restrict__ Qp, __half* __restrict__ Kp, __half* __restrict__ Vt,
    float qscale)
{
    __shared__ __half As[GBM * GLDH];
    __shared__ __half Bs[GBN * GLDH];
    const int z = blockIdx.z;
    const float* A  = (z == 0) ? q  : (z == 1) ? k  : v;
    const float* W  = (z == 0) ? Wq : (z == 1) ? Wk : Wv;
    const float* bb = (z == 0) ? bq : (z == 1) ? bk : bv;
    __half* C       = (z == 0) ? Qp : (z == 1) ? Kp : Vt;
    const float sc  = (z == 0) ? qscale : 1.0f;
    gemm_body<__half>(A, W, bb, C, sc, z == 2, As, Bs);
}

__global__ __launch_bounds__(256, 2) void o_gemm(
    const float* __restrict__ Ctx, const float* __restrict__ Wo,
    const float* __restrict__ bo, float* __restrict__ out)
{
    __shared__ __half As[GBM * GLDH];
    __shared__ __half Bs[GBN * GLDH];
    gemm_body<float>(Ctx, Wo, bo, out, 1.0f, 0, As, Bs);
}

// ---------------------------------------------------------------------------
// Attention (Round-11 proven structure + ldmatrix.x4 B-fragment loads).
// fp16 mma, 32-q warp tiles, 2-stage cp.async, exp2-domain softmax via
// ex2.f16x2, row sums via ones-MMA. One ldmatrix.x4 = b0/b1 for TWO mmas.
// CTA = (b, h, 128-query tile), 128 threads = 4 warps x 32 q-rows.
// ---------------------------------------------------------------------------
#define KLD 72
#define NT  (SEQ / 64)
#define BUFB (128 * KLD * 2)      // bytes per KV buffer

__global__ void __launch_bounds__(128, 3)
attn_tc(const __half* __restrict__ Qp, const __half* __restrict__ Kp,
        const __half* __restrict__ Vt, const int* __restrict__ mask,
        float* __restrict__ Ctx)
{
    __shared__ __half KV[2][128 * KLD];

    const int tid = threadIdx.x;
    const int lane = tid & 31, wid = tid >> 5;
    const int g = lane >> 2, tig = lane & 3;
    const int b = blockIdx.y / HEADS, h = blockIdx.y % HEADS;
    const int q0 = blockIdx.x * 128;
    const int qb = wid * 32;

    const __half* kg = Kp + ((size_t)b * SEQ) * DMODEL + h * DK;
    const __half* vg = Vt + ((size_t)(b * DMODEL + h * DK)) * SEQ;
    const int* mg = mask + b * SEQ;

    // ---- stage Q (fp16, pre-scaled) through KV[0], lift A-frags ----
    {
        const __half* qg = Qp + ((size_t)(b * SEQ + q0)) * DMODEL + h * DK;
        #pragma unroll
        for (int i = 0; i < 8; i++) {
            const int L = tid + i * 128;
            const int r = L >> 3, c8 = (L & 7) * 8;
            *(uint4*)(KV[0] + r * KLD + c8) =
                *(const uint4*)(qg + (size_t)r * DMODEL + c8);
        }
    }
    __syncthreads();

    uint32_t qf[4][2][4];
    #pragma unroll
    for (int c = 0; c < 4; c++) {
        const int kk = 16 * c + 2 * tig;
        #pragma unroll
        for (int i = 0; i < 2; i++) {
            const int rb = qb + 16 * i;
            qf[c][i][0] = *(const uint32_t*)&KV[0][(rb + g) * KLD + kk];
            qf[c][i][1] = *(const uint32_t*)&KV[0][(rb + 8 + g) * KLD + kk];
            qf[c][i][2] = *(const uint32_t*)&KV[0][(rb + g) * KLD + kk + 8];
            qf[c][i][3] = *(const uint32_t*)&KV[0][(rb + 8 + g) * KLD + kk + 8];
        }
    }
    __syncthreads();

    // ---- hoisted prefetch addressing ----
    const int pr = tid >> 3;
    const int pc = (tid & 7) * 8;
    const __half* ksrc = kg + (size_t)pr * DMODEL + pc;
    const __half* vsrc = vg + (size_t)pr * SEQ + pc;
    const uint32_t dk0 =
        (uint32_t)__cvta_generic_to_shared(&KV[0][pr * KLD + pc]);

    // ---- ldmatrix per-lane base address (loop-invariant) ----
    // x4 tiles for (c, jp): [j=2jp,k+0..7], [j,k+8..15], [j+1,k..], [j+1,k+8..]
    const int sel = lane >> 3;                       // 0..3
    const int lrow = (sel >> 1) * 8 + (lane & 7);    // row within j-pair
    const int lcol = (sel & 1) * 8;                  // k-half offset
    const uint32_t lmK0 =
        (uint32_t)__cvta_generic_to_shared(&KV[0][lrow * KLD + lcol]);

    float o[2][8][4] = {};
    float lacc[2][4] = {};
    const uint32_t ONE2 = 0x3C003C00u;
    const float NEGINF = __int_as_float(0xff800000);

    // prefetch tile 0 into buffer 0
    {
        const uint32_t dV = dk0 + 64 * KLD * 2;
        #pragma unroll
        for (int i = 0; i < 4; i++) {
            cpa16r(dk0 + i * (16 * KLD * 2), ksrc + (size_t)i * 16 * DMODEL);
            cpa16r(dV + i * (16 * KLD * 2), vsrc + (size_t)i * 16 * SEQ);
        }
        CPA_COMMIT();
        ksrc += (size_t)64 * DMODEL;
        vsrc += 64;
    }

    for (int kt = 0; kt < NT; kt++) {
        const int cur = kt & 1;
        const uint32_t kbase = lmK0 + cur * BUFB;
        const uint32_t vbase = kbase + 64 * KLD * 2;

        const int mv = __ldg(mg + kt * 64 + (tid & 63));

        if (kt + 1 < NT) {
            const uint32_t dK = dk0 + (cur ^ 1) * BUFB;
            const uint32_t dV = dK + 64 * KLD * 2;
            #pragma unroll
            for (int i = 0; i < 4; i++) {
                cpa16r(dK + i * (16 * KLD * 2), ksrc + (size_t)i * 16 * DMODEL);
                cpa16r(dV + i * (16 * KLD * 2), vsrc + (size_t)i * 16 * SEQ);
            }
            CPA_COMMIT();
            ksrc += (size_t)64 * DMODEL;
            vsrc += 64;
            CPA_WAIT1();
        } else {
            CPA_WAIT0();
        }
        const int allone = __syncthreads_and(mv != 0);

        // ---- S = Q K^T (exp2-domain scores), B via ldmatrix.x4 ----
        float s[2][8][4] = {};
        #pragma unroll
        for (int c = 0; c < 4; c++) {
            #pragma unroll
            for (int jp = 0; jp < 4; jp++) {
                uint32_t b00, b01, b10, b11;
                ldsm4(b00, b01, b10, b11,
                      kbase + (uint32_t)(c * 16 + jp * 16 * KLD) * 2);
                mma16(s[0][2 * jp],     qf[c][0], b00, b01);
                mma16(s[1][2 * jp],     qf[c][1], b00, b01);
                mma16(s[0][2 * jp + 1], qf[c][0], b10, b11);
                mma16(s[1][2 * jp + 1], qf[c][1], b10, b11);
            }
        }

        // ---- mask (rare path): poison scores with -inf ----
        if (!allone) {
            #pragma unroll
            for (int j = 0; j < 8; j++) {
                int2 mi = __ldg((const int2*)(mg + kt * 64 + j * 8 + 2 * tig));
                if (!mi.x) {
                    s[0][j][0] = NEGINF; s[0][j][2] = NEGINF;
                    s[1][j][0] = NEGINF; s[1][j][2] = NEGINF;
                }
                if (!mi.y) {
                    s[0][j][1] = NEGINF; s[0][j][3] = NEGINF;
                    s[1][j][1] = NEGINF; s[1][j][3] = NEGINF;
                }
            }
        }

        // ---- p = exp2(s) in f16x2; result IS the P fragment ----
        uint32_t pa[2][8][2];
        #pragma unroll
        for (int j = 0; j < 8; j++) {
            pa[0][j][0] = ex2h2(packh2(s[0][j][0], s[0][j][1]));
            pa[0][j][1] = ex2h2(packh2(s[0][j][2], s[0][j][3]));
            pa[1][j][0] = ex2h2(packh2(s[1][j][0], s[1][j][1]));
            pa[1][j][1] = ex2h2(packh2(s[1][j][2], s[1][j][3]));
        }

        // ---- O += P V^T ; l += P·1 (ones-MMA); B via ldmatrix.x4 ----
        #pragma unroll
        for (int m = 0; m < 4; m++) {
            uint32_t av0[4] = { pa[0][2 * m][0], pa[0][2 * m][1],
                                pa[0][2 * m + 1][0], pa[0][2 * m + 1][1] };
            uint32_t av1[4] = { pa[1][2 * m][0], pa[1][2 * m][1],
                                pa[1][2 * m + 1][0], pa[1][2 * m + 1][1] };
            #pragma unroll
            for (int jp = 0; jp < 4; jp++) {
                uint32_t b00, b01, b10, b11;
                ldsm4(b00, b01, b10, b11,
                      vbase + (uint32_t)(m * 16 + jp * 16 * KLD) * 2);
                mma16(o[0][2 * jp],     av0, b00, b01);
                mma16(o[1][2 * jp],     av1, b00, b01);
                mma16(o[0][2 * jp + 1], av0, b10, b11);
                mma16(o[1][2 * jp + 1], av1, b10, b11);
            }
            mma16(lacc[0], av0, ONE2, ONE2);
            mma16(lacc[1], av1, ONE2, ONE2);
        }
        __syncthreads();
    }

    // ---- finalize ----
    const float inv[2][2] = { {1.f / lacc[0][0], 1.f / lacc[0][2]},
                              {1.f / lacc[1][0], 1.f / lacc[1][2]} };

    #pragma unroll
    for (int i = 0; i < 2; i++) {
        float* cg = Ctx + ((size_t)(b * SEQ + q0 + qb + 16 * i)) * DMODEL + h * DK;
        #pragma unroll
        for (int j = 0; j < 8; j++) {
            const int col = j * 8 + 2 * tig;
            *(float2*)(cg + (size_t)g * DMODEL + col) =
                make_float2(o[i][j][0] * inv[i][0], o[i][j][1] * inv[i][0]);
            *(float2*)(cg + (size_t)(8 + g) * DMODEL + col) =
                make_float2(o[i][j][2] * inv[i][1], o[i][j][3] * inv[i][1]);
        }
    }
}

// ---------------------------------------------------------------------------
// Launcher.  Inputs: q, k, v, Wq, bq, Wk, bk, Wv, bv, Wo, bo, mask
// ---------------------------------------------------------------------------
extern "C" void kernel_launch(void* const* d_in, const int* in_sizes, int n_in,
                              void* d_out, int out_size)
{
    const float* q    = (const float*)d_in[0];
    const float* k    = (const float*)d_in[1];
    const float* v    = (const float*)d_in[2];
    const float* Wq   = (const float*)d_in[3];
    const float* bq   = (const float*)d_in[4];
    const float* Wk   = (const float*)d_in[5];
    const float* bk   = (const float*)d_in[6];
    const float* Wv   = (const float*)d_in[7];
    const float* bv   = (const float*)d_in[8];
    const float* Wo   = (const float*)d_in[9];
    const float* bo   = (const float*)d_in[10];
    const int*   mask = (const int*)d_in[11];
    float* out = (float*)d_out;

    __half *Qp, *Kp, *Vt;
    float *Ctx;
    cudaGetSymbolAddress((void**)&Qp,  g_Qp);
    cudaGetSymbolAddress((void**)&Kp,  g_Kp);
    cudaGetSymbolAddress((void**)&Vt,  g_Vt);
    cudaGetSymbolAddress((void**)&Ctx, g_Ctx);

    // Q scale folds 1/sqrt(dk) AND log2(e): scores emerge in exp2 domain.
    const float qscale = 0.125f * 1.44269504088896340736f;

    dim3 qkvgrid(DMODEL / GBN, MROWS / GBM, 3);   // (6, 64, 3)
    qkv_gemm<<<qkvgrid, 256>>>(q, k, v, Wq, bq, Wk, bk, Wv, bv,
                               Qp, Kp, Vt, qscale);

    dim3 agrid(SEQ / 128, BS * HEADS);            // (32, 24)
    attn_tc<<<agrid, 128>>>(Qp, Kp, Vt, mask, Ctx);

    dim3 ogrid(DMODEL / GBN, MROWS / GBM);        // (6, 64)
    o_gemm<<<ogrid, 256>>>(Ctx, Wo, bo, out);
}

// round 16
// speedup vs baseline: 1.1620x; 1.0200x over previous
#include <cuda_runtime.h>
#include <cuda_fp16.h>
#include <cstdint>

// ---------------------------------------------------------------------------
// Problem constants
// ---------------------------------------------------------------------------
#define BS      2
#define SEQ     4096
#define DMODEL  768
#define HEADS   12
#define DK      64
#define MROWS   (BS * SEQ)          // 8192

// ---------------------------------------------------------------------------
// Scratch (device globals; no cudaMalloc allowed)
// ---------------------------------------------------------------------------
__device__ __half g_Qp[MROWS * DMODEL];              // prescaled by log2e/8
__device__ __half g_Kp[MROWS * DMODEL];
__device__ __half g_Vt[(size_t)BS * DMODEL * SEQ];   // [b][dmodel][seq]
__device__ float  g_Ctx[MROWS * DMODEL];

// ---------------------------------------------------------------------------
// Helpers
// ---------------------------------------------------------------------------
__device__ __forceinline__ void mma16(float* d, const uint32_t* a,
                                      uint32_t b0, uint32_t b1) {
    asm volatile(
        "mma.sync.aligned.m16n8k16.row.col.f32.f16.f16.f32 "
        "{%0,%1,%2,%3}, {%4,%5,%6,%7}, {%8,%9}, {%0,%1,%2,%3};"
        : "+f"(d[0]), "+f"(d[1]), "+f"(d[2]), "+f"(d[3])
        : "r"(a[0]), "r"(a[1]), "r"(a[2]), "r"(a[3]), "r"(b0), "r"(b1));
}

__device__ __forceinline__ uint32_t packh2(float a, float b) {
    __half2 h = __floats2half2_rn(a, b);
    return *(uint32_t*)&h;
}

__device__ __forceinline__ uint32_t ex2h2(uint32_t x) {
    uint32_t r;
    asm("ex2.approx.f16x2 %0, %1;" : "=r"(r) : "r"(x));
    return r;
}

__device__ __forceinline__ void st_h4(__half* p, float4 v) {
    uint2 u;
    u.x = packh2(v.x, v.y);
    u.y = packh2(v.z, v.w);
    *(uint2*)p = u;
}

__device__ __forceinline__ void cpa16r(uint32_t dst, const void* src) {
    asm volatile("cp.async.cg.shared.global [%0], [%1], 16;"
                 :: "r"(dst), "l"(src));
}
#define CPA_COMMIT() asm volatile("cp.async.commit_group;" ::: "memory")
#define CPA_WAIT1()  asm volatile("cp.async.wait_group 1;" ::: "memory")
#define CPA_WAIT0()  asm volatile("cp.async.wait_group 0;" ::: "memory")

// ldmatrix x4: four 8x8 b16 tiles in one instruction
__device__ __forceinline__ void ldsm4(uint32_t& r0, uint32_t& r1,
                                      uint32_t& r2, uint32_t& r3,
                                      uint32_t addr) {
    asm volatile("ldmatrix.sync.aligned.m8n8.x4.shared.b16 {%0,%1,%2,%3}, [%4];"
                 : "=r"(r0), "=r"(r1), "=r"(r2), "=r"(r3) : "r"(addr));
}

// ---------------------------------------------------------------------------
// GEMM: C[M,N] = (A @ B^T + bias)*scale, fp32 in, fp16 smem staging,
// 128x128 tile, BK=32, 256 threads, warp tile 32x64.
// Fragment loads via ldmatrix.x4 (12 LDSM per warp per k32 vs 48 LDS.32).
// trans!=0: write C transposed per batch (Vt layout).
// ---------------------------------------------------------------------------
#define GBM 128
#define GBN 128
#define GBK 32
#define GLDH 40

template <typename OutT>
__device__ __forceinline__ void gemm_body(
    const float* __restrict__ A, const float* __restrict__ B,
    const float* __restrict__ bias, OutT* __restrict__ C,
    float scale, int trans, __half* As, __half* Bs)
{
    const int N = DMODEL, K = DMODEL;
    const int tid = threadIdx.x;
    const int lane = tid & 31, wid = tid >> 5;
    const int g = lane >> 2, tig = lane & 3;
    const int wm = (wid & 3) * 32, wn = (wid >> 2) * 64;
    const int row0 = blockIdx.y * GBM, col0 = blockIdx.x * GBN;

    const int r = tid >> 3;
    const int c4 = (tid & 7) * 4;
    const float* Aptr = A + (size_t)(row0 + r) * K + c4;
    const float* Bptr = B + (size_t)(col0 + r) * K + c4;

    // ---- hoisted ldmatrix lane addresses (loop-invariant) ----
    // A tile order: rows0-7@klo, rows8-15@klo, rows0-7@khi, rows8-15@khi
    const int arow = (lane & 7) + ((lane >> 3) & 1) * 8;
    const int acol = (lane >> 4) * 8;
    const uint32_t aBase = (uint32_t)__cvta_generic_to_shared(
        &As[(wm + arow) * GLDH + acol]);
    // B tile order: rows0-7@klo, rows0-7@khi, rows8-15@klo, rows8-15@khi
    const int brow = ((lane >> 4) & 1) * 8 + (lane & 7);
    const int bcol = ((lane >> 3) & 1) * 8;
    const uint32_t bBase = (uint32_t)__cvta_generic_to_shared(
        &Bs[(wn + brow) * GLDH + bcol]);

    float4 pa[4], pb[4];
    #pragma unroll
    for (int m = 0; m < 4; m++) {
        pa[m] = *(const float4*)(Aptr + (size_t)(32 * m) * K);
        pb[m] = *(const float4*)(Bptr + (size_t)(32 * m) * K);
    }

    float acc[2][8][4] = {};

    int k0 = 0;
    while (true) {
        __syncthreads();
        #pragma unroll
        for (int m = 0; m < 4; m++) {
            st_h4(As + (r + 32 * m) * GLDH + c4, pa[m]);
            st_h4(Bs + (r + 32 * m) * GLDH + c4, pb[m]);
        }
        __syncthreads();

        k0 += GBK;
        const bool more = (k0 < K);
        if (more) {
            #pragma unroll
            for (int m = 0; m < 4; m++) {
                pa[m] = *(const float4*)(Aptr + (size_t)(32 * m) * K + k0);
                pb[m] = *(const float4*)(Bptr + (size_t)(32 * m) * K + k0);
            }
        }

        #pragma unroll
        for (int c = 0; c < 2; c++) {
            uint32_t a[2][4];
            #pragma unroll
            for (int i = 0; i < 2; i++)
                ldsm4(a[i][0], a[i][1], a[i][2], a[i][3],
                      aBase + (uint32_t)(i * 16 * GLDH + 16 * c) * 2);
            #pragma unroll
            for (int jp = 0; jp < 4; jp++) {
                uint32_t b00, b01, b10, b11;
                ldsm4(b00, b01, b10, b11,
                      bBase + (uint32_t)(jp * 16 * GLDH + 16 * c) * 2);
                mma16(acc[0][2 * jp],     a[0], b00, b01);
                mma16(acc[1][2 * jp],     a[1], b00, b01);
                mma16(acc[0][2 * jp + 1], a[0], b10, b11);
                mma16(acc[1][2 * jp + 1], a[1], b10, b11);
            }
        }
        if (!more) break;
    }

    #pragma unroll
    for (int i = 0; i < 2; i++) {
        const int rA = row0 + wm + i * 16 + g;
        const int rB = rA + 8;
        #pragma unroll
        for (int j = 0; j < 8; j++) {
            const int col = col0 + wn + j * 8 + 2 * tig;
            const float bx = __ldg(bias + col), by = __ldg(bias + col + 1);
            const float v0 = (acc[i][j][0] + bx) * scale;
            const float v1 = (acc[i][j][1] + by) * scale;
            const float v2 = (acc[i][j][2] + bx) * scale;
            const float v3 = (acc[i][j][3] + by) * scale;
            if (!trans) {
                if (sizeof(OutT) == 2) {
                    __half2* pA = (__half2*)((__half*)C + (size_t)rA * N + col);
                    __half2* pB = (__half2*)((__half*)C + (size_t)rB * N + col);
                    *pA = __floats2half2_rn(v0, v1);
                    *pB = __floats2half2_rn(v2, v3);
                } else {
                    *(float2*)((float*)C + (size_t)rA * N + col) = make_float2(v0, v1);
                    *(float2*)((float*)C + (size_t)rB * N + col) = make_float2(v2, v3);
                }
            } else {
                const int bA = rA >> 12, sA = rA & (SEQ - 1);
                const int bB = rB >> 12, sB = rB & (SEQ - 1);
                C[((size_t)bA * DMODEL + col)     * SEQ + sA] = (OutT)v0;
                C[((size_t)bA * DMODEL + col + 1) * SEQ + sA] = (OutT)v1;
                C[((size_t)bB * DMODEL + col)     * SEQ + sB] = (OutT)v2;
                C[((size_t)bB * DMODEL + col + 1) * SEQ + sB] = (OutT)v3;
            }
        }
    }
}

// merged Q/K/V projection: blockIdx.z selects the GEMM
__global__ __launch_bounds__(256, 2) void qkv_gemm(
    const float* __restrict__ q, const float* __restrict__ k,
    const float* __restrict__ v,
    const float* __restrict__ Wq, const float* __restrict__ bq,
    const float* __restrict__ Wk, const float* __restrict__ bk,
    const float* __restrict__ Wv, const float* __restrict__ bv,
    __half* __restrict__ Qp, __half* __restrict__ Kp, __half* __restrict__ Vt,
    float qscale)
{
    __shared__ __half As[GBM * GLDH];
    __shared__ __half Bs[GBN * GLDH];
    const int z = blockIdx.z;
    const float* A  = (z == 0) ? q  : (z == 1) ? k  : v;
    const float* W  = (z == 0) ? Wq : (z == 1) ? Wk : Wv;
    const float* bb = (z == 0) ? bq : (z == 1) ? bk : bv;
    __half* C       = (z == 0) ? Qp : (z == 1) ? Kp : Vt;
    const float sc  = (z == 0) ? qscale : 1.0f;
    gemm_body<__half>(A, W, bb, C, sc, z == 2, As, Bs);
}

__global__ __launch_bounds__(256, 2) void o_gemm(
    const float* __restrict__ Ctx, const float* __restrict__ Wo,
    const float* __restrict__ bo, float* __restrict__ out)
{
    __shared__ __half As[GBM * GLDH];
    __shared__ __half Bs[GBN * GLDH];
    gemm_body<float>(Ctx, Wo, bo, out, 1.0f, 0, As, Bs);
}

// ---------------------------------------------------------------------------
// Attention (Round-15 proven, unchanged): fp16 mma, 32-q warp tiles,
// 2-stage cp.async, exp2-domain softmax via ex2.f16x2, ones-MMA row sums,
// ldmatrix.x4 B-fragment loads.
// ---------------------------------------------------------------------------
#define KLD 72
#define NT  (SEQ / 64)
#define BUFB (128 * KLD * 2)      // bytes per KV buffer

__global__ void __launch_bounds__(128, 3)
attn_tc(const __half* __restrict__ Qp, const __half* __restrict__ Kp,
        const __half* __restrict__ Vt, const int* __restrict__ mask,
        float* __restrict__ Ctx)
{
    __shared__ __half KV[2][128 * KLD];

    const int tid = threadIdx.x;
    const int lane = tid & 31, wid = tid >> 5;
    const int g = lane >> 2, tig = lane & 3;
    const int b = blockIdx.y / HEADS, h = blockIdx.y % HEADS;
    const int q0 = blockIdx.x * 128;
    const int qb = wid * 32;

    const __half* kg = Kp + ((size_t)b * SEQ) * DMODEL + h * DK;
    const __half* vg = Vt + ((size_t)(b * DMODEL + h * DK)) * SEQ;
    const int* mg = mask + b * SEQ;

    // ---- stage Q (fp16, pre-scaled) through KV[0], lift A-frags ----
    {
        const __half* qg = Qp + ((size_t)(b * SEQ + q0)) * DMODEL + h * DK;
        #pragma unroll
        for (int i = 0; i < 8; i++) {
            const int L = tid + i * 128;
            const int r = L >> 3, c8 = (L & 7) * 8;
            *(uint4*)(KV[0] + r * KLD + c8) =
                *(const uint4*)(qg + (size_t)r * DMODEL + c8);
        }
    }
    __syncthreads();

    uint32_t qf[4][2][4];
    #pragma unroll
    for (int c = 0; c < 4; c++) {
        const int kk = 16 * c + 2 * tig;
        #pragma unroll
        for (int i = 0; i < 2; i++) {
            const int rb = qb + 16 * i;
            qf[c][i][0] = *(const uint32_t*)&KV[0][(rb + g) * KLD + kk];
            qf[c][i][1] = *(const uint32_t*)&KV[0][(rb + 8 + g) * KLD + kk];
            qf[c][i][2] = *(const uint32_t*)&KV[0][(rb + g) * KLD + kk + 8];
            qf[c][i][3] = *(const uint32_t*)&KV[0][(rb + 8 + g) * KLD + kk + 8];
        }
    }
    __syncthreads();

    // ---- hoisted prefetch addressing ----
    const int pr = tid >> 3;
    const int pc = (tid & 7) * 8;
    const __half* ksrc = kg + (size_t)pr * DMODEL + pc;
    const __half* vsrc = vg + (size_t)pr * SEQ + pc;
    const uint32_t dk0 =
        (uint32_t)__cvta_generic_to_shared(&KV[0][pr * KLD + pc]);

    // ---- ldmatrix per-lane base address (loop-invariant) ----
    const int sel = lane >> 3;
    const int lrow = (sel >> 1) * 8 + (lane & 7);
    const int lcol = (sel & 1) * 8;
    const uint32_t lmK0 =
        (uint32_t)__cvta_generic_to_shared(&KV[0][lrow * KLD + lcol]);

    float o[2][8][4] = {};
    float lacc[2][4] = {};
    const uint32_t ONE2 = 0x3C003C00u;
    const float NEGINF = __int_as_float(0xff800000);

    // prefetch tile 0 into buffer 0
    {
        const uint32_t dV = dk0 + 64 * KLD * 2;
        #pragma unroll
        for (int i = 0; i < 4; i++) {
            cpa16r(dk0 + i * (16 * KLD * 2), ksrc + (size_t)i * 16 * DMODEL);
            cpa16r(dV + i * (16 * KLD * 2), vsrc + (size_t)i * 16 * SEQ);
        }
        CPA_COMMIT();
        ksrc += (size_t)64 * DMODEL;
        vsrc += 64;
    }

    for (int kt = 0; kt < NT; kt++) {
        const int cur = kt & 1;
        const uint32_t kbase = lmK0 + cur * BUFB;
        const uint32_t vbase = kbase + 64 * KLD * 2;

        const int mv = __ldg(mg + kt * 64 + (tid & 63));

        if (kt + 1 < NT) {
            const uint32_t dK = dk0 + (cur ^ 1) * BUFB;
            const uint32_t dV = dK + 64 * KLD * 2;
            #pragma unroll
            for (int i = 0; i < 4; i++) {
                cpa16r(dK + i * (16 * KLD * 2), ksrc + (size_t)i * 16 * DMODEL);
                cpa16r(dV + i * (16 * KLD * 2), vsrc + (size_t)i * 16 * SEQ);
            }
            CPA_COMMIT();
            ksrc += (size_t)64 * DMODEL;
            vsrc += 64;
            CPA_WAIT1();
        } else {
            CPA_WAIT0();
        }
        const int allone = __syncthreads_and(mv != 0);

        // ---- S = Q K^T (exp2-domain scores), B via ldmatrix.x4 ----
        float s[2][8][4] = {};
        #pragma unroll
        for (int c = 0; c < 4; c++) {
            #pragma unroll
            for (int jp = 0; jp < 4; jp++) {
                uint32_t b00, b01, b10, b11;
                ldsm4(b00, b01, b10, b11,
                      kbase + (uint32_t)(c * 16 + jp * 16 * KLD) * 2);
                mma16(s[0][2 * jp],     qf[c][0], b00, b01);
                mma16(s[1][2 * jp],     qf[c][1], b00, b01);
                mma16(s[0][2 * jp + 1], qf[c][0], b10, b11);
                mma16(s[1][2 * jp + 1], qf[c][1], b10, b11);
            }
        }

        // ---- mask (rare path): poison scores with -inf ----
        if (!allone) {
            #pragma unroll
            for (int j = 0; j < 8; j++) {
                int2 mi = __ldg((const int2*)(mg + kt * 64 + j * 8 + 2 * tig));
                if (!mi.x) {
                    s[0][j][0] = NEGINF; s[0][j][2] = NEGINF;
                    s[1][j][0] = NEGINF; s[1][j][2] = NEGINF;
                }
                if (!mi.y) {
                    s[0][j][1] = NEGINF; s[0][j][3] = NEGINF;
                    s[1][j][1] = NEGINF; s[1][j][3] = NEGINF;
                }
            }
        }

        // ---- p = exp2(s) in f16x2; result IS the P fragment ----
        uint32_t pa[2][8][2];
        #pragma unroll
        for (int j = 0; j < 8; j++) {
            pa[0][j][0] = ex2h2(packh2(s[0][j][0], s[0][j][1]));
            pa[0][j][1] = ex2h2(packh2(s[0][j][2], s[0][j][3]));
            pa[1][j][0] = ex2h2(packh2(s[1][j][0], s[1][j][1]));
            pa[1][j][1] = ex2h2(packh2(s[1][j][2], s[1][j][3]));
        }

        // ---- O += P V^T ; l += P·1 (ones-MMA); B via ldmatrix.x4 ----
        #pragma unroll
        for (int m = 0; m < 4; m++) {
            uint32_t av0[4] = { pa[0][2 * m][0], pa[0][2 * m][1],
                                pa[0][2 * m + 1][0], pa[0][2 * m + 1][1] };
            uint32_t av1[4] = { pa[1][2 * m][0], pa[1][2 * m][1],
                                pa[1][2 * m + 1][0], pa[1][2 * m + 1][1] };
            #pragma unroll
            for (int jp = 0; jp < 4; jp++) {
                uint32_t b00, b01, b10, b11;
                ldsm4(b00, b01, b10, b11,
                      vbase + (uint32_t)(m * 16 + jp * 16 * KLD) * 2);
                mma16(o[0][2 * jp],     av0, b00, b01);
                mma16(o[1][2 * jp],     av1, b00, b01);
                mma16(o[0][2 * jp + 1], av0, b10, b11);
                mma16(o[1][2 * jp + 1], av1, b10, b11);
            }
            mma16(lacc[0], av0, ONE2, ONE2);
            mma16(lacc[1], av1, ONE2, ONE2);
        }
        __syncthreads();
    }

    // ---- finalize ----
    const float inv[2][2] = { {1.f / lacc[0][0], 1.f / lacc[0][2]},
                              {1.f / lacc[1][0], 1.f / lacc[1][2]} };

    #pragma unroll
    for (int i = 0; i < 2; i++) {
        float* cg = Ctx + ((size_t)(b * SEQ + q0 + qb + 16 * i)) * DMODEL + h * DK;
        #pragma unroll
        for (int j = 0; j < 8; j++) {
            const int col = j * 8 + 2 * tig;
            *(float2*)(cg + (size_t)g * DMODEL + col) =
                make_float2(o[i][j][0] * inv[i][0], o[i][j][1] * inv[i][0]);
            *(float2*)(cg + (size_t)(8 + g) * DMODEL + col) =
                make_float2(o[i][j][2] * inv[i][1], o[i][j][3] * inv[i][1]);
        }
    }
}

// ---------------------------------------------------------------------------
// Launcher.  Inputs: q, k, v, Wq, bq, Wk, bk, Wv, bv, Wo, bo, mask
// ---------------------------------------------------------------------------
extern "C" void kernel_launch(void* const* d_in, const int* in_sizes, int n_in,
                              void* d_out, int out_size)
{
    const float* q    = (const float*)d_in[0];
    const float* k    = (const float*)d_in[1];
    const float* v    = (const float*)d_in[2];
    const float* Wq   = (const float*)d_in[3];
    const float* bq   = (const float*)d_in[4];
    const float* Wk   = (const float*)d_in[5];
    const float* bk   = (const float*)d_in[6];
    const float* Wv   = (const float*)d_in[7];
    const float* bv   = (const float*)d_in[8];
    const float* Wo   = (const float*)d_in[9];
    const float* bo   = (const float*)d_in[10];
    const int*   mask = (const int*)d_in[11];
    float* out = (float*)d_out;

    __half *Qp, *Kp, *Vt;
    float *Ctx;
    cudaGetSymbolAddress((void**)&Qp,  g_Qp);
    cudaGetSymbolAddress((void**)&Kp,  g_Kp);
    cudaGetSymbolAddress((void**)&Vt,  g_Vt);
    cudaGetSymbolAddress((void**)&Ctx, g_Ctx);

    // Q scale folds 1/sqrt(dk) AND log2(e): scores emerge in exp2 domain.
    const float qscale = 0.125f * 1.44269504088896340736f;

    dim3 qkvgrid(DMODEL / GBN, MROWS / GBM, 3);   // (6, 64, 3)
    qkv_gemm<<<qkvgrid, 256>>>(q, k, v, Wq, bq, Wk, bk, Wv, bv,
                               Qp, Kp, Vt, qscale);

    dim3 agrid(SEQ / 128, BS * HEADS);            // (32, 24)
    attn_tc<<<agrid, 128>>>(Qp, Kp, Vt, mask, Ctx);

    dim3 ogrid(DMODEL / GBN, MROWS / GBM);        // (6, 64)
    o_gemm<<<ogrid, 256>>>(Ctx, Wo, bo, out);
}

// round 17
// speedup vs baseline: 1.2268x; 1.0558x over previous
#include <cuda_runtime.h>
#include <cuda_fp16.h>
#include <cstdint>

// ---------------------------------------------------------------------------
// Problem constants
// ---------------------------------------------------------------------------
#define BS      2
#define SEQ     4096
#define DMODEL  768
#define HEADS   12
#define DK      64
#define MROWS   (BS * SEQ)          // 8192

// ---------------------------------------------------------------------------
// Scratch (device globals; no cudaMalloc allowed)
// ---------------------------------------------------------------------------
__device__ __half g_Qp[MROWS * DMODEL];              // prescaled by log2e/8
__device__ __half g_Kp[MROWS * DMODEL];
__device__ __half g_Vt[(size_t)BS * DMODEL * SEQ];   // [b][dmodel][seq]
__device__ __half g_Ctx[MROWS * DMODEL];             // fp16 context

// ---------------------------------------------------------------------------
// Helpers
// ---------------------------------------------------------------------------
__device__ __forceinline__ void mma16(float* d, const uint32_t* a,
                                      uint32_t b0, uint32_t b1) {
    asm volatile(
        "mma.sync.aligned.m16n8k16.row.col.f32.f16.f16.f32 "
        "{%0,%1,%2,%3}, {%4,%5,%6,%7}, {%8,%9}, {%0,%1,%2,%3};"
        : "+f"(d[0]), "+f"(d[1]), "+f"(d[2]), "+f"(d[3])
        : "r"(a[0]), "r"(a[1]), "r"(a[2]), "r"(a[3]), "r"(b0), "r"(b1));
}

__device__ __forceinline__ uint32_t packh2(float a, float b) {
    __half2 h = __floats2half2_rn(a, b);
    return *(uint32_t*)&h;
}

__device__ __forceinline__ uint32_t ex2h2(uint32_t x) {
    uint32_t r;
    asm("ex2.approx.f16x2 %0, %1;" : "=r"(r) : "r"(x));
    return r;
}

__device__ __forceinline__ void st_h4(__half* p, float4 v) {
    uint2 u;
    u.x = packh2(v.x, v.y);
    u.y = packh2(v.z, v.w);
    *(uint2*)p = u;
}

__device__ __forceinline__ void cpa16r(uint32_t dst, const void* src) {
    asm volatile("cp.async.cg.shared.global [%0], [%1], 16;"
                 :: "r"(dst), "l"(src));
}
#define CPA_COMMIT() asm volatile("cp.async.commit_group;" ::: "memory")
#define CPA_WAIT1()  asm volatile("cp.async.wait_group 1;" ::: "memory")
#define CPA_WAIT0()  asm volatile("cp.async.wait_group 0;" ::: "memory")

// ldmatrix x4: four 8x8 b16 tiles in one instruction
__device__ __forceinline__ void ldsm4(uint32_t& r0, uint32_t& r1,
                                      uint32_t& r2, uint32_t& r3,
                                      uint32_t addr) {
    asm volatile("ldmatrix.sync.aligned.m8n8.x4.shared.b16 {%0,%1,%2,%3}, [%4];"
                 : "=r"(r0), "=r"(r1), "=r"(r2), "=r"(r3) : "r"(addr));
}

// ---------------------------------------------------------------------------
// GEMM: C[M,N] = (A @ B^T + bias)*scale. A is fp32 OR fp16 (AT); B (weights)
// fp32. fp16 smem staging, 128x128 tile, BK=32, 256 threads, warp tile 32x64,
// ldmatrix.x4 fragment loads, DOUBLE-BUFFERED smem (one barrier per k-iter).
// trans!=0: write C transposed per batch (Vt layout).
// ---------------------------------------------------------------------------
#define GBM 128
#define GBN 128
#define GBK 32
#define GLDH 40
#define GBUFE (128 * GLDH)        // elements per stage buffer
#define GBUFB (GBUFE * 2)         // bytes per stage buffer

template <typename AT, typename OutT>
__device__ __forceinline__ void gemm_body(
    const AT* __restrict__ A, const float* __restrict__ B,
    const float* __restrict__ bias, OutT* __restrict__ C,
    float scale, int trans, __half* As, __half* Bs)   // As,Bs: [2][GBUFE]
{
    const int N = DMODEL, K = DMODEL;
    const int tid = threadIdx.x;
    const int lane = tid & 31, wid = tid >> 5;
    const int g = lane >> 2, tig = lane & 3;
    const int wm = (wid & 3) * 32, wn = (wid >> 2) * 64;
    const int row0 = blockIdx.y * GBM, col0 = blockIdx.x * GBN;

    const int r = tid >> 3;
    const int c4 = (tid & 7) * 4;
    const AT*    Aptr = A + (size_t)(row0 + r) * K + c4;
    const float* Bptr = B + (size_t)(col0 + r) * K + c4;

    // ---- hoisted ldmatrix lane addresses (buffer 0) ----
    const int arow = (lane & 7) + ((lane >> 3) & 1) * 8;
    const int acol = (lane >> 4) * 8;
    const uint32_t aBase = (uint32_t)__cvta_generic_to_shared(
        &As[(wm + arow) * GLDH + acol]);
    const int brow = ((lane >> 4) & 1) * 8 + (lane & 7);
    const int bcol = ((lane >> 3) & 1) * 8;
    const uint32_t bBase = (uint32_t)__cvta_generic_to_shared(
        &Bs[(wn + brow) * GLDH + bcol]);

    float4 pa[4], pb[4];
    uint2  ph[4];

    // ---- ldg tile k0 into regs ----
    auto ldg_tile = [&](int k0) {
        #pragma unroll
        for (int m = 0; m < 4; m++) {
            if (sizeof(AT) == 4)
                pa[m] = *(const float4*)((const float*)Aptr
                                         + (size_t)(32 * m) * K + k0);
            else
                ph[m] = *(const uint2*)((const __half*)Aptr
                                        + (size_t)(32 * m) * K + k0);
            pb[m] = *(const float4*)(Bptr + (size_t)(32 * m) * K + k0);
        }
    };
    // ---- store staged regs into buffer `buf` ----
    auto sts_tile = [&](int buf) {
        __half* Ad = As + buf * GBUFE + r * GLDH + c4;
        __half* Bd = Bs + buf * GBUFE + r * GLDH + c4;
        #pragma unroll
        for (int m = 0; m < 4; m++) {
            if (sizeof(AT) == 4) st_h4(Ad + 32 * m * GLDH, pa[m]);
            else *(uint2*)(Ad + 32 * m * GLDH) = ph[m];
            st_h4(Bd + 32 * m * GLDH, pb[m]);
        }
    };

    float acc[2][8][4] = {};
    const int NKT = K / GBK;   // 24

    // prologue: stage tile 0, prefetch tile 1
    ldg_tile(0);
    sts_tile(0);
    ldg_tile(GBK);
    __syncthreads();

    for (int kt = 0; kt < NKT; kt++) {
        const int cur = kt & 1;
        const uint32_t aB = aBase + cur * GBUFB;
        const uint32_t bB = bBase + cur * GBUFB;

        #pragma unroll
        for (int c = 0; c < 2; c++) {
            uint32_t a[2][4];
            #pragma unroll
            for (int i = 0; i < 2; i++)
                ldsm4(a[i][0], a[i][1], a[i][2], a[i][3],
                      aB + (uint32_t)(i * 16 * GLDH + 16 * c) * 2);
            #pragma unroll
            for (int jp = 0; jp < 4; jp++) {
                uint32_t b00, b01, b10, b11;
                ldsm4(b00, b01, b10, b11,
                      bB + (uint32_t)(jp * 16 * GLDH + 16 * c) * 2);
                mma16(acc[0][2 * jp],     a[0], b00, b01);
                mma16(acc[1][2 * jp],     a[1], b00, b01);
                mma16(acc[0][2 * jp + 1], a[0], b10, b11);
                mma16(acc[1][2 * jp + 1], a[1], b10, b11);
            }
        }

        if (kt + 1 < NKT) {
            sts_tile(cur ^ 1);                    // buf^1 free since kt-1 bar
            if (kt + 2 < NKT) ldg_tile((kt + 2) * GBK);
            __syncthreads();                      // one barrier per iter
        }
    }

    #pragma unroll
    for (int i = 0; i < 2; i++) {
        const int rA = row0 + wm + i * 16 + g;
        const int rB = rA + 8;
        #pragma unroll
        for (int j = 0; j < 8; j++) {
            const int col = col0 + wn + j * 8 + 2 * tig;
            const float bx = __ldg(bias + col), by = __ldg(bias + col + 1);
            const float v0 = (acc[i][j][0] + bx) * scale;
            const float v1 = (acc[i][j][1] + by) * scale;
            const float v2 = (acc[i][j][2] + bx) * scale;
            const float v3 = (acc[i][j][3] + by) * scale;
            if (!trans) {
                if (sizeof(OutT) == 2) {
                    __half2* pA2 = (__half2*)((__half*)C + (size_t)rA * N + col);
                    __half2* pB2 = (__half2*)((__half*)C + (size_t)rB * N + col);
                    *pA2 = __floats2half2_rn(v0, v1);
                    *pB2 = __floats2half2_rn(v2, v3);
                } else {
                    *(float2*)((float*)C + (size_t)rA * N + col) = make_float2(v0, v1);
                    *(float2*)((float*)C + (size_t)rB * N + col) = make_float2(v2, v3);
                }
            } else {
                const int bA = rA >> 12, sA = rA & (SEQ - 1);
                const int bB2 = rB >> 12, sB = rB & (SEQ - 1);
                C[((size_t)bA * DMODEL + col)      * SEQ + sA] = (OutT)v0;
                C[((size_t)bA * DMODEL + col + 1)  * SEQ + sA] = (OutT)v1;
                C[((size_t)bB2 * DMODEL + col)     * SEQ + sB] = (OutT)v2;
                C[((size_t)bB2 * DMODEL + col + 1) * SEQ + sB] = (OutT)v3;
            }
        }
    }
}

// merged Q/K/V projection: blockIdx.z selects the GEMM
__global__ __launch_bounds__(256, 2) void qkv_gemm(
    const float* __restrict__ q, const float* __restrict__ k,
    const float* __restrict__ v,
    const float* __restrict__ Wq, const float* __restrict__ bq,
    const float* __restrict__ Wk, const float* __restrict__ bk,
    const float* __restrict__ Wv, const float* __restrict__ bv,
    __half* __restrict__ Qp, __half* __restrict__ Kp, __half* __restrict__ Vt,
    float qscale)
{
    __shared__ __half As[2 * GBUFE];
    __shared__ __half Bs[2 * GBUFE];
    const int z = blockIdx.z;
    const float* A  = (z == 0) ? q  : (z == 1) ? k  : v;
    const float* W  = (z == 0) ? Wq : (z == 1) ? Wk : Wv;
    const float* bb = (z == 0) ? bq : (z == 1) ? bk : bv;
    __half* C       = (z == 0) ? Qp : (z == 1) ? Kp : Vt;
    const float sc  = (z == 0) ? qscale : 1.0f;
    gemm_body<float, __half>(A, W, bb, C, sc, z == 2, As, Bs);
}

__global__ __launch_bounds__(256, 2) void o_gemm(
    const __half* __restrict__ Ctx, const float* __restrict__ Wo,
    const float* __restrict__ bo, float* __restrict__ out)
{
    __shared__ __half As[2 * GBUFE];
    __shared__ __half Bs[2 * GBUFE];
    gemm_body<__half, float>(Ctx, Wo, bo, out, 1.0f, 0, As, Bs);
}

// ---------------------------------------------------------------------------
// Attention (Round-15/16 proven): fp16 mma, 32-q warp tiles, 2-stage
// cp.async, exp2-domain softmax via ex2.f16x2, ones-MMA row sums,
// ldmatrix.x4 B-fragment loads. Ctx written as fp16.
// ---------------------------------------------------------------------------
#define KLD 72
#define NT  (SEQ / 64)
#define BUFB (128 * KLD * 2)      // bytes per KV buffer

__global__ void __launch_bounds__(128, 3)
attn_tc(const __half* __restrict__ Qp, const __half* __restrict__ Kp,
        const __half* __restrict__ Vt, const int* __restrict__ mask,
        __half* __restrict__ Ctx)
{
    __shared__ __half KV[2][128 * KLD];

    const int tid = threadIdx.x;
    const int lane = tid & 31, wid = tid >> 5;
    const int g = lane >> 2, tig = lane & 3;
    const int b = blockIdx.y / HEADS, h = blockIdx.y % HEADS;
    const int q0 = blockIdx.x * 128;
    const int qb = wid * 32;

    const __half* kg = Kp + ((size_t)b * SEQ) * DMODEL + h * DK;
    const __half* vg = Vt + ((size_t)(b * DMODEL + h * DK)) * SEQ;
    const int* mg = mask + b * SEQ;

    // ---- stage Q (fp16, pre-scaled) through KV[0], lift A-frags ----
    {
        const __half* qg = Qp + ((size_t)(b * SEQ + q0)) * DMODEL + h * DK;
        #pragma unroll
        for (int i = 0; i < 8; i++) {
            const int L = tid + i * 128;
            const int r = L >> 3, c8 = (L & 7) * 8;
            *(uint4*)(KV[0] + r * KLD + c8) =
                *(const uint4*)(qg + (size_t)r * DMODEL + c8);
        }
    }
    __syncthreads();

    uint32_t qf[4][2][4];
    #pragma unroll
    for (int c = 0; c < 4; c++) {
        const int kk = 16 * c + 2 * tig;
        #pragma unroll
        for (int i = 0; i < 2; i++) {
            const int rb = qb + 16 * i;
            qf[c][i][0] = *(const uint32_t*)&KV[0][(rb + g) * KLD + kk];
            qf[c][i][1] = *(const uint32_t*)&KV[0][(rb + 8 + g) * KLD + kk];
            qf[c][i][2] = *(const uint32_t*)&KV[0][(rb + g) * KLD + kk + 8];
            qf[c][i][3] = *(const uint32_t*)&KV[0][(rb + 8 + g) * KLD + kk + 8];
        }
    }
    __syncthreads();

    // ---- hoisted prefetch addressing ----
    const int pr = tid >> 3;
    const int pc = (tid & 7) * 8;
    const __half* ksrc = kg + (size_t)pr * DMODEL + pc;
    const __half* vsrc = vg + (size_t)pr * SEQ + pc;
    const uint32_t dk0 =
        (uint32_t)__cvta_generic_to_shared(&KV[0][pr * KLD + pc]);

    // ---- ldmatrix per-lane base address (loop-invariant) ----
    const int sel = lane >> 3;
    const int lrow = (sel >> 1) * 8 + (lane & 7);
    const int lcol = (sel & 1) * 8;
    const uint32_t lmK0 =
        (uint32_t)__cvta_generic_to_shared(&KV[0][lrow * KLD + lcol]);

    float o[2][8][4] = {};
    float lacc[2][4] = {};
    const uint32_t ONE2 = 0x3C003C00u;
    const float NEGINF = __int_as_float(0xff800000);

    // prefetch tile 0 into buffer 0
    {
        const uint32_t dV = dk0 + 64 * KLD * 2;
        #pragma unroll
        for (int i = 0; i < 4; i++) {
            cpa16r(dk0 + i * (16 * KLD * 2), ksrc + (size_t)i * 16 * DMODEL);
            cpa16r(dV + i * (16 * KLD * 2), vsrc + (size_t)i * 16 * SEQ);
        }
        CPA_COMMIT();
        ksrc += (size_t)64 * DMODEL;
        vsrc += 64;
    }

    for (int kt = 0; kt < NT; kt++) {
        const int cur = kt & 1;
        const uint32_t kbase = lmK0 + cur * BUFB;
        const uint32_t vbase = kbase + 64 * KLD * 2;

        const int mv = __ldg(mg + kt * 64 + (tid & 63));

        if (kt + 1 < NT) {
            const uint32_t dK = dk0 + (cur ^ 1) * BUFB;
            const uint32_t dV = dK + 64 * KLD * 2;
            #pragma unroll
            for (int i = 0; i < 4; i++) {
                cpa16r(dK + i * (16 * KLD * 2), ksrc + (size_t)i * 16 * DMODEL);
                cpa16r(dV + i * (16 * KLD * 2), vsrc + (size_t)i * 16 * SEQ);
            }
            CPA_COMMIT();
            ksrc += (size_t)64 * DMODEL;
            vsrc += 64;
            CPA_WAIT1();
        } else {
            CPA_WAIT0();
        }
        const int allone = __syncthreads_and(mv != 0);

        // ---- S = Q K^T (exp2-domain scores), B via ldmatrix.x4 ----
        float s[2][8][4] = {};
        #pragma unroll
        for (int c = 0; c < 4; c++) {
            #pragma unroll
            for (int jp = 0; jp < 4; jp++) {
                uint32_t b00, b01, b10, b11;
                ldsm4(b00, b01, b10, b11,
                      kbase + (uint32_t)(c * 16 + jp * 16 * KLD) * 2);
                mma16(s[0][2 * jp],     qf[c][0], b00, b01);
                mma16(s[1][2 * jp],     qf[c][1], b00, b01);
                mma16(s[0][2 * jp + 1], qf[c][0], b10, b11);
                mma16(s[1][2 * jp + 1], qf[c][1], b10, b11);
            }
        }

        // ---- mask (rare path): poison scores with -inf ----
        if (!allone) {
            #pragma unroll
            for (int j = 0; j < 8; j++) {
                int2 mi = __ldg((const int2*)(mg + kt * 64 + j * 8 + 2 * tig));
                if (!mi.x) {
                    s[0][j][0] = NEGINF; s[0][j][2] = NEGINF;
                    s[1][j][0] = NEGINF; s[1][j][2] = NEGINF;
                }
                if (!mi.y) {
                    s[0][j][1] = NEGINF; s[0][j][3] = NEGINF;
                    s[1][j][1] = NEGINF; s[1][j][3] = NEGINF;
                }
            }
        }

        // ---- p = exp2(s) in f16x2; result IS the P fragment ----
        uint32_t pa[2][8][2];
        #pragma unroll
        for (int j = 0; j < 8; j++) {
            pa[0][j][0] = ex2h2(packh2(s[0][j][0], s[0][j][1]));
            pa[0][j][1] = ex2h2(packh2(s[0][j][2], s[0][j][3]));
            pa[1][j][0] = ex2h2(packh2(s[1][j][0], s[1][j][1]));
            pa[1][j][1] = ex2h2(packh2(s[1][j][2], s[1][j][3]));
        }

        // ---- O += P V^T ; l += P·1 (ones-MMA); B via ldmatrix.x4 ----
        #pragma unroll
        for (int m = 0; m < 4; m++) {
            uint32_t av0[4] = { pa[0][2 * m][0], pa[0][2 * m][1],
                                pa[0][2 * m + 1][0], pa[0][2 * m + 1][1] };
            uint32_t av1[4] = { pa[1][2 * m][0], pa[1][2 * m][1],
                                pa[1][2 * m + 1][0], pa[1][2 * m + 1][1] };
            #pragma unroll
            for (int jp = 0; jp < 4; jp++) {
                uint32_t b00, b01, b10, b11;
                ldsm4(b00, b01, b10, b11,
                      vbase + (uint32_t)(m * 16 + jp * 16 * KLD) * 2);
                mma16(o[0][2 * jp],     av0, b00, b01);
                mma16(o[1][2 * jp],     av1, b00, b01);
                mma16(o[0][2 * jp + 1], av0, b10, b11);
                mma16(o[1][2 * jp + 1], av1, b10, b11);
            }
            mma16(lacc[0], av0, ONE2, ONE2);
            mma16(lacc[1], av1, ONE2, ONE2);
        }
        __syncthreads();
    }

    // ---- finalize: Ctx written as fp16 ----
    const float inv[2][2] = { {1.f / lacc[0][0], 1.f / lacc[0][2]},
                              {1.f / lacc[1][0], 1.f / lacc[1][2]} };

    #pragma unroll
    for (int i = 0; i < 2; i++) {
        __half* cg = Ctx + ((size_t)(b * SEQ + q0 + qb + 16 * i)) * DMODEL + h * DK;
        #pragma unroll
        for (int j = 0; j < 8; j++) {
            const int col = j * 8 + 2 * tig;
            *(__half2*)(cg + (size_t)g * DMODEL + col) =
                __floats2half2_rn(o[i][j][0] * inv[i][0],
                                  o[i][j][1] * inv[i][0]);
            *(__half2*)(cg + (size_t)(8 + g) * DMODEL + col) =
                __floats2half2_rn(o[i][j][2] * inv[i][1],
                                  o[i][j][3] * inv[i][1]);
        }
    }
}

// ---------------------------------------------------------------------------
// Launcher.  Inputs: q, k, v, Wq, bq, Wk, bk, Wv, bv, Wo, bo, mask
// ---------------------------------------------------------------------------
extern "C" void kernel_launch(void* const* d_in, const int* in_sizes, int n_in,
                              void* d_out, int out_size)
{
    const float* q    = (const float*)d_in[0];
    const float* k    = (const float*)d_in[1];
    const float* v    = (const float*)d_in[2];
    const float* Wq   = (const float*)d_in[3];
    const float* bq   = (const float*)d_in[4];
    const float* Wk   = (const float*)d_in[5];
    const float* bk   = (const float*)d_in[6];
    const float* Wv   = (const float*)d_in[7];
    const float* bv   = (const float*)d_in[8];
    const float* Wo   = (const float*)d_in[9];
    const float* bo   = (const float*)d_in[10];
    const int*   mask = (const int*)d_in[11];
    float* out = (float*)d_out;

    __half *Qp, *Kp, *Vt, *Ctx;
    cudaGetSymbolAddress((void**)&Qp,  g_Qp);
    cudaGetSymbolAddress((void**)&Kp,  g_Kp);
    cudaGetSymbolAddress((void**)&Vt,  g_Vt);
    cudaGetSymbolAddress((void**)&Ctx, g_Ctx);

    // Q scale folds 1/sqrt(dk) AND log2(e): scores emerge in exp2 domain.
    const float qscale = 0.125f * 1.44269504088896340736f;

    dim3 qkvgrid(DMODEL / GBN, MROWS / GBM, 3);   // (6, 64, 3)
    qkv_gemm<<<qkvgrid, 256>>>(q, k, v, Wq, bq, Wk, bk, Wv, bv,
                               Qp, Kp, Vt, qscale);

    dim3 agrid(SEQ / 128, BS * HEADS);            // (32, 24)
    attn_tc<<<agrid, 128>>>(Qp, Kp, Vt, mask, Ctx);

    dim3 ogrid(DMODEL / GBN, MROWS / GBM);        // (6, 64)
    o_gemm<<<ogrid, 256>>>(Ctx, Wo, bo, out);
}